// round 7
// baseline (speedup 1.0000x reference)
#include <cuda_runtime.h>
#include <cuda_fp16.h>
#include <cstdint>

#define NQ   2048
#define ND   100000
#define NDP  100096          // 782 * 128
#define DIM  128
#define KSEL 10
#define M32  32              // exact-rescore pool size per query
#define NTILE 782
#define NCAND (NTILE * KSEL) // 7820 candidates per query

// ---------------- scratch (static __device__) ----------------------------------
__device__ float  g_x2w[NDP];                   // ||x||^2 - w  (pad rows = +inf)
__device__ __half g_Ah[NQ * DIM];               // fp16 of (-2 * x_tilde)
__device__ __half g_Xh[(size_t)NDP * DIM];      // fp16 of X (pad rows = 0)
__device__ __align__(16) float2 g_cand[(size_t)NQ * NCAND]; // (approx val, bitcast idx)
__device__ __align__(16) float2 g_c32[(size_t)NQ * M32];

__device__ __forceinline__ uint32_t smem_u32(const void* p) {
    uint32_t a;
    asm("{ .reg .u64 t; cvta.to.shared.u64 t, %1; cvt.u32.u64 %0, t; }" : "=r"(a) : "l"(p));
    return a;
}
__device__ __forceinline__ void ldsm4(uint32_t* r, uint32_t addr) {
    asm volatile("ldmatrix.sync.aligned.m8n8.x4.shared.b16 {%0,%1,%2,%3}, [%4];"
        : "=r"(r[0]), "=r"(r[1]), "=r"(r[2]), "=r"(r[3]) : "r"(addr));
}
__device__ __forceinline__ void mma16816(float* c, const uint32_t* a, const uint32_t* b) {
    asm volatile("mma.sync.aligned.m16n8k16.row.col.f32.f16.f16.f32 "
        "{%0,%1,%2,%3}, {%4,%5,%6,%7}, {%8,%9}, {%0,%1,%2,%3};"
        : "+f"(c[0]), "+f"(c[1]), "+f"(c[2]), "+f"(c[3])
        : "r"(a[0]), "r"(a[1]), "r"(a[2]), "r"(a[3]), "r"(b[0]), "r"(b[1]));
}
__device__ __forceinline__ uint32_t swzc(uint32_t ck, uint32_t s) {
    return ((ck ^ s) & 7u) | (ck & 8u);
}
__device__ __forceinline__ void cp16(uint32_t dst, const void* src) {
    asm volatile("cp.async.cg.shared.global [%0], [%1], 16;" :: "r"(dst), "l"(src));
}
__device__ __forceinline__ void cp_commit() { asm volatile("cp.async.commit_group;"); }
__device__ __forceinline__ void cp_wait0()  { asm volatile("cp.async.wait_group 0;" ::: "memory"); }

// ---------------------------------------------------------------------------
// Kernel 1: norms + fp16 conversion (q scaled by -2, X padded to NDP).
// ---------------------------------------------------------------------------
__global__ void prep_kernel(const float* __restrict__ X,
                            const float* __restrict__ w,
                            const float* __restrict__ q) {
    int gw   = (blockIdx.x * 256 + threadIdx.x) >> 5;
    int lane = threadIdx.x & 31;
    if (gw < NDP) {
        if (gw < ND) {
            float4 v = reinterpret_cast<const float4*>(X + (size_t)gw * DIM)[lane];
            float s = v.x * v.x + v.y * v.y + v.z * v.z + v.w * v.w;
            #pragma unroll
            for (int o = 16; o > 0; o >>= 1) s += __shfl_xor_sync(0xffffffffu, s, o);
            __half2* dh = reinterpret_cast<__half2*>(g_Xh + (size_t)gw * DIM + lane * 4);
            dh[0] = __halves2half2(__float2half_rn(v.x), __float2half_rn(v.y));
            dh[1] = __halves2half2(__float2half_rn(v.z), __float2half_rn(v.w));
            if (lane == 0) g_x2w[gw] = s - w[gw];
        } else {
            __half2 z = __halves2half2(__float2half(0.f), __float2half(0.f));
            __half2* dh = reinterpret_cast<__half2*>(g_Xh + (size_t)gw * DIM + lane * 4);
            dh[0] = z; dh[1] = z;
            if (lane == 0) g_x2w[gw] = __int_as_float(0x7f800000);  // +inf
        }
    } else if (gw < NDP + NQ) {
        int r = gw - NDP;
        float4 v = reinterpret_cast<const float4*>(q + (size_t)r * DIM)[lane];
        __half2* dh = reinterpret_cast<__half2*>(g_Ah + (size_t)r * DIM + lane * 4);
        dh[0] = __halves2half2(__float2half_rn(-2.f * v.x), __float2half_rn(-2.f * v.y));
        dh[1] = __halves2half2(__float2half_rn(-2.f * v.z), __float2half_rn(-2.f * v.w));
    }
}

// ---------------------------------------------------------------------------
// Kernel 2: fused 1-term HMMA GEMM + per-tile top-10 compaction -> g_cand.
// CTA = 128x128 tile, 256 threads, 2 CTAs/SM (tail overlaps co-CTA's MMA).
// ---------------------------------------------------------------------------
#define SA_H 0
#define SB_H 32768
#define SROWB 528                      // padded score row (132 floats)
#define SSCORE 0                       // reuses staging; 128*528 = 67584
#define SX2   67584                    // 128 floats
#define SSCRATCH 68096                 // 256 threads * 10 * 8B = 20480
#define SMEM_TOTAL (68096 + 20480)     // 88576

__global__ void __launch_bounds__(256, 2)
gemm_fused_kernel() {
    extern __shared__ char smem[];
    const uint32_t sb = smem_u32(smem);
    const int t = threadIdx.x, lane = t & 31, wid = t >> 5;
    const int m0 = blockIdx.x * 128, n0 = blockIdx.y * 128;
    const int wm = (wid >> 2) * 64, wn = (wid & 3) * 32;

    if (t < 128) reinterpret_cast<float*>(smem + SX2)[t] = g_x2w[n0 + t];

    // stage Ah + Bh via cp.async (swizzled)
    #pragma unroll
    for (int i = 0; i < 16; i++) {
        int id = t + 256 * i;
        int tile = id >> 11;            // 0=Ah 1=Bh
        int within = id & 2047;
        int row = within >> 4, c = within & 15;
        const __half* src = tile ? g_Xh : g_Ah;
        int grow = (tile ? n0 : m0) + row;
        uint32_t dst = sb + (tile ? SB_H : SA_H) + row * 256 + swzc((uint32_t)c, row & 7) * 16;
        cp16(dst, reinterpret_cast<const char*>(src) + (size_t)grow * 256 + c * 16);
    }
    cp_commit();

    uint32_t aOff[4], aS[4];
    #pragma unroll
    for (int mf = 0; mf < 4; mf++) {
        int r = wm + mf * 16 + (lane & 15);
        aOff[mf] = (uint32_t)r * 256; aS[mf] = r & 7;
    }
    uint32_t bOff[2], bS[2];
    #pragma unroll
    for (int p = 0; p < 2; p++) {
        int r = wn + p * 16 + (lane & 7) + ((lane >> 4) << 3);
        bOff[p] = (uint32_t)r * 256; bS[p] = r & 7;
    }
    const uint32_t aHi = (lane >> 4) & 1;
    const uint32_t bHi = (lane >> 3) & 1;

    float acc[4][4][4];
    #pragma unroll
    for (int mf = 0; mf < 4; mf++)
        #pragma unroll
        for (int nf = 0; nf < 4; nf++)
            #pragma unroll
            for (int e = 0; e < 4; e++) acc[mf][nf][e] = 0.f;

    cp_wait0();
    __syncthreads();

    #pragma unroll
    for (int c8 = 0; c8 < 8; c8++) {
        uint32_t ah[4][4], bh[2][4];
        uint32_t ckA = 2 * c8 + aHi, ckB = 2 * c8 + bHi;
        #pragma unroll
        for (int mf = 0; mf < 4; mf++) ldsm4(ah[mf], sb + SA_H + aOff[mf] + swzc(ckA, aS[mf]) * 16);
        #pragma unroll
        for (int p = 0; p < 2; p++)    ldsm4(bh[p], sb + SB_H + bOff[p] + swzc(ckB, bS[p]) * 16);
        #pragma unroll
        for (int mf = 0; mf < 4; mf++)
            #pragma unroll
            for (int nf = 0; nf < 4; nf++)
                mma16816(acc[mf][nf], ah[mf], &bh[nf >> 1][(nf & 1) * 2]);
    }
    __syncthreads();      // all ldsm reads done -> staging becomes score tile

    // ---- write raw scores to smem (row stride 528B)
    {
        const int g = lane >> 2, tig = lane & 3;
        #pragma unroll
        for (int mf = 0; mf < 4; mf++) {
            int r0 = wm + mf * 16 + g;
            #pragma unroll
            for (int nf = 0; nf < 4; nf++) {
                int nl = wn + nf * 8 + tig * 2;
                *reinterpret_cast<float2*>(smem + SSCORE + r0 * SROWB + nl * 4) =
                    make_float2(acc[mf][nf][0], acc[mf][nf][1]);
                *reinterpret_cast<float2*>(smem + SSCORE + (r0 + 8) * SROWB + nl * 4) =
                    make_float2(acc[mf][nf][2], acc[mf][nf][3]);
            }
        }
    }
    __syncthreads();

    // ---- per-row top-10: 2 threads/row scan 64 each (+x2w), then pair-merge
    {
        const int row = t >> 1, half = t & 1;
        const float* srow = reinterpret_cast<const float*>(smem + SSCORE + row * SROWB) + half * 64;
        const float* x2s  = reinterpret_cast<const float*>(smem + SX2) + half * 64;
        float bv[KSEL]; int bi[KSEL];
        #pragma unroll
        for (int r = 0; r < KSEL; r++) { bv[r] = __int_as_float(0x7f800000); bi[r] = 0; }
        #pragma unroll
        for (int j4 = 0; j4 < 16; j4++) {
            float4 v = reinterpret_cast<const float4*>(srow)[j4];
            float4 xw = reinterpret_cast<const float4*>(x2s)[j4];
            float vv[4] = {v.x + xw.x, v.y + xw.y, v.z + xw.z, v.w + xw.w};
            #pragma unroll
            for (int e = 0; e < 4; e++) {
                float x = vv[e];
                if (x < bv[KSEL - 1]) {
                    float cv = x; int ci = n0 + half * 64 + j4 * 4 + e;
                    #pragma unroll
                    for (int r = 0; r < KSEL; r++) {
                        if (cv < bv[r]) {
                            float tv = bv[r]; bv[r] = cv; cv = tv;
                            int ti = bi[r]; bi[r] = ci; ci = ti;
                        }
                    }
                }
            }
        }
        float2* scr = reinterpret_cast<float2*>(smem + SSCRATCH) + t * KSEL;
        #pragma unroll
        for (int r = 0; r < KSEL; r++) scr[r] = make_float2(bv[r], __int_as_float(bi[r]));
    }
    __syncthreads();
    if (t < 128) {
        const float2* scr = reinterpret_cast<const float2*>(smem + SSCRATCH) + (2 * t) * KSEL;
        float bv[KSEL]; int bi[KSEL];
        #pragma unroll
        for (int r = 0; r < KSEL; r++) { bv[r] = __int_as_float(0x7f800000); bi[r] = 0; }
        #pragma unroll
        for (int e = 0; e < 2 * KSEL; e++) {
            float2 c = scr[e];
            if (c.x < bv[KSEL - 1]) {
                float cv = c.x; int ci = __float_as_int(c.y);
                #pragma unroll
                for (int r = 0; r < KSEL; r++) {
                    if (cv < bv[r]) {
                        float tv = bv[r]; bv[r] = cv; cv = tv;
                        int ti = bi[r]; bi[r] = ci; ci = ti;
                    }
                }
            }
        }
        float2* dst = g_cand + (size_t)(m0 + t) * NCAND + blockIdx.y * KSEL;
        #pragma unroll
        for (int r = 0; r < KSEL; r++)
            __stcs(&dst[r], make_float2(bv[r], __int_as_float(bi[r])));
    }
}

// ---------------------------------------------------------------------------
// Kernel 3: merge 7820 candidates/query -> approx top-32 -> g_c32.
// ---------------------------------------------------------------------------
__global__ void __launch_bounds__(256, 1)
select_kernel() {
    const int b = blockIdx.x;
    const int t = threadIdx.x;
    const float4* c4 = reinterpret_cast<const float4*>(g_cand + (size_t)b * NCAND);

    float bv[KSEL]; int bi[KSEL];
    #pragma unroll
    for (int r = 0; r < KSEL; r++) { bv[r] = __int_as_float(0x7f800000); bi[r] = 0; }

    for (int j = t; j < NCAND / 2; j += 256) {      // float4 = 2 candidates
        float4 v = __ldcs(&c4[j]);
        float xs[2]  = {v.x, v.z};
        int   ixs[2] = {__float_as_int(v.y), __float_as_int(v.w)};
        #pragma unroll
        for (int e = 0; e < 2; e++) {
            float x = xs[e];
            if (x < bv[KSEL - 1]) {
                float cv = x; int ci = ixs[e];
                #pragma unroll
                for (int r = 0; r < KSEL; r++) {
                    if (cv < bv[r]) {
                        float tv = bv[r]; bv[r] = cv; cv = tv;
                        int ti = bi[r]; bi[r] = ci; ci = ti;
                    }
                }
            }
        }
    }

    __shared__ float sv[256 * (KSEL + 1)];
    __shared__ int   si[256 * (KSEL + 1)];
    __shared__ float redv[256];
    __shared__ int   redt[256];
    __shared__ float selv[M32];
    __shared__ int   seli[M32];

    #pragma unroll
    for (int r = 0; r < KSEL; r++) {
        sv[t * (KSEL + 1) + r] = bv[r];
        si[t * (KSEL + 1) + r] = bi[r];
    }
    sv[t * (KSEL + 1) + KSEL] = __int_as_float(0x7f800000);  // sentinel
    __syncthreads();

    int h = 0;
    for (int r = 0; r < M32; r++) {
        redv[t] = sv[t * (KSEL + 1) + h];
        redt[t] = t;
        __syncthreads();
        #pragma unroll
        for (int s = 128; s > 0; s >>= 1) {
            if (t < s) {
                if (redv[t + s] < redv[t]) { redv[t] = redv[t + s]; redt[t] = redt[t + s]; }
            }
            __syncthreads();
        }
        if (t == redt[0]) {
            selv[r] = sv[t * (KSEL + 1) + h];
            seli[r] = si[t * (KSEL + 1) + h];
            if (h < KSEL) h++;                    // clamp at sentinel
        }
        __syncthreads();
    }

    if (t < M32)
        g_c32[(size_t)b * M32 + t] = make_float2(selv[t], __int_as_float(seli[t]));
}

// ---------------------------------------------------------------------------
// Kernel 4: exact fp32 rescore of 32 candidates -> final outputs.
// ---------------------------------------------------------------------------
__global__ void __launch_bounds__(128, 8)
rescore_kernel(const float* __restrict__ X, const float* __restrict__ q,
               const float* __restrict__ w, float* __restrict__ out) {
    const int b = blockIdx.x;
    const int t = threadIdx.x, lane = t & 31, wid = t >> 5;

    __shared__ float qs[DIM];
    __shared__ float cs[M32];    // srank = d2 - w
    __shared__ float cf[M32];    // f = w - sqrt(d2)
    __shared__ int   ci[M32];

    qs[t] = q[(size_t)b * DIM + t];
    __syncthreads();

    const float4* q4 = reinterpret_cast<const float4*>(qs);
    #pragma unroll
    for (int c = 0; c < 8; c++) {
        int slot = wid * 8 + c;
        int idx = __float_as_int(g_c32[(size_t)b * M32 + slot].y);
        float4 xv = reinterpret_cast<const float4*>(X + (size_t)idx * DIM)[lane];
        float4 qv = q4[lane];
        float dx = qv.x - xv.x, dy = qv.y - xv.y, dz = qv.z - xv.z, dw = qv.w - xv.w;
        float d = dx * dx + dy * dy + dz * dz + dw * dw;
        #pragma unroll
        for (int o = 16; o > 0; o >>= 1) d += __shfl_xor_sync(0xffffffffu, d, o);
        if (lane == 0) {
            float wn = w[idx];
            cs[slot] = d - wn;
            cf[slot] = wn - sqrtf(fmaxf(d, 0.0f));
            ci[slot] = idx;
        }
    }
    __syncthreads();

    if (t == 0) {
        float bv[KSEL]; int bs[KSEL];
        #pragma unroll
        for (int r = 0; r < KSEL; r++) { bv[r] = __int_as_float(0x7f800000); bs[r] = -1; }
        #pragma unroll
        for (int e = 0; e < M32; e++) {
            float x = cs[e];
            if (x < bv[KSEL - 1]) {
                float cv = x; int cslot = e;
                #pragma unroll
                for (int r = 0; r < KSEL; r++) {
                    if (cv < bv[r]) {
                        float tv = bv[r]; bv[r] = cv; cv = tv;
                        int ts = bs[r]; bs[r] = cslot; cslot = ts;
                    }
                }
            }
        }
        float bestf = __int_as_float(0xff800000);
        int besti = 0;
        #pragma unroll
        for (int r = 0; r < KSEL; r++) {
            int s = bs[r];
            if (s >= 0) {
                float f = cf[s];
                if (f > bestf) { bestf = f; besti = ci[s]; }
            }
        }
        out[b]      = bestf;
        out[NQ + b] = (float)besti;
    }
}

extern "C" void kernel_launch(void* const* d_in, const int* in_sizes, int n_in,
                              void* d_out, int out_size) {
    const float* q = (const float*)d_in[0];   // x_tilde [2048,128]
    const float* X = (const float*)d_in[1];   // X [100000,128]
    const float* w = (const float*)d_in[2];   // w [100000,1]
    float* out = (float*)d_out;

    cudaFuncSetAttribute(gemm_fused_kernel,
                         cudaFuncAttributeMaxDynamicSharedMemorySize, SMEM_TOTAL);

    prep_kernel<<<(NDP + NQ) / 8, 256>>>(X, w, q);
    dim3 g(NQ / 128, NTILE);                  // m fastest: 16 CTAs share each X tile in L2
    gemm_fused_kernel<<<g, 256, SMEM_TOTAL>>>();
    select_kernel<<<NQ, 256>>>();
    rescore_kernel<<<NQ, 128>>>(X, q, w, out);
}

// round 9
// speedup vs baseline: 1.3327x; 1.3327x over previous
#include <cuda_runtime.h>
#include <cuda_fp16.h>
#include <cstdint>

#define NQ   2048
#define ND   100000
#define NDP  100096          // 782 * 128
#define DIM  128
#define KSEL 10
#define M32  32              // exact-rescore pool size per query

// ---------------- scratch (static __device__) ----------------------------------
__device__ float  g_x2w[NDP];                   // ||x||^2 - w  (pad rows = +inf)
__device__ __half g_Ah[NQ * DIM];               // fp16 of (-2 * x_tilde)
__device__ __half g_Xh[(size_t)NDP * DIM];      // fp16 of X (pad rows = 0)
__device__ __half g_s[(size_t)NQ * NDP];        // approx score matrix (fp16)
__device__ __align__(16) float2 g_c32[(size_t)NQ * M32];  // (approx val, bitcast idx)

__device__ __forceinline__ uint32_t smem_u32(const void* p) {
    uint32_t a;
    asm("{ .reg .u64 t; cvta.to.shared.u64 t, %1; cvt.u32.u64 %0, t; }" : "=r"(a) : "l"(p));
    return a;
}
__device__ __forceinline__ void ldsm4(uint32_t* r, uint32_t addr) {
    asm volatile("ldmatrix.sync.aligned.m8n8.x4.shared.b16 {%0,%1,%2,%3}, [%4];"
        : "=r"(r[0]), "=r"(r[1]), "=r"(r[2]), "=r"(r[3]) : "r"(addr));
}
__device__ __forceinline__ void mma16816(float* c, const uint32_t* a, const uint32_t* b) {
    asm volatile("mma.sync.aligned.m16n8k16.row.col.f32.f16.f16.f32 "
        "{%0,%1,%2,%3}, {%4,%5,%6,%7}, {%8,%9}, {%0,%1,%2,%3};"
        : "+f"(c[0]), "+f"(c[1]), "+f"(c[2]), "+f"(c[3])
        : "r"(a[0]), "r"(a[1]), "r"(a[2]), "r"(a[3]), "r"(b[0]), "r"(b[1]));
}
__device__ __forceinline__ uint32_t swzc(uint32_t ck, uint32_t s) {
    return ((ck ^ s) & 7u) | (ck & 8u);
}
__device__ __forceinline__ void cp16(uint32_t dst, const void* src) {
    asm volatile("cp.async.cg.shared.global [%0], [%1], 16;" :: "r"(dst), "l"(src));
}
__device__ __forceinline__ void cp_commit() { asm volatile("cp.async.commit_group;"); }
__device__ __forceinline__ void cp_wait0()  { asm volatile("cp.async.wait_group 0;" ::: "memory"); }
__device__ __forceinline__ void stcs32(void* p, uint32_t v) {
    asm volatile("st.global.cs.b32 [%0], %1;" :: "l"(p), "r"(v));
}

// ---------------------------------------------------------------------------
// Kernel 1: norms + fp16 conversion (q scaled by -2, X padded to NDP).
// ---------------------------------------------------------------------------
__global__ void prep_kernel(const float* __restrict__ X,
                            const float* __restrict__ w,
                            const float* __restrict__ q) {
    int gw   = (blockIdx.x * 256 + threadIdx.x) >> 5;
    int lane = threadIdx.x & 31;
    if (gw < NDP) {
        if (gw < ND) {
            float4 v = reinterpret_cast<const float4*>(X + (size_t)gw * DIM)[lane];
            float s = v.x * v.x + v.y * v.y + v.z * v.z + v.w * v.w;
            #pragma unroll
            for (int o = 16; o > 0; o >>= 1) s += __shfl_xor_sync(0xffffffffu, s, o);
            __half2* dh = reinterpret_cast<__half2*>(g_Xh + (size_t)gw * DIM + lane * 4);
            dh[0] = __halves2half2(__float2half_rn(v.x), __float2half_rn(v.y));
            dh[1] = __halves2half2(__float2half_rn(v.z), __float2half_rn(v.w));
            if (lane == 0) g_x2w[gw] = s - w[gw];
        } else {
            __half2 z = __halves2half2(__float2half(0.f), __float2half(0.f));
            __half2* dh = reinterpret_cast<__half2*>(g_Xh + (size_t)gw * DIM + lane * 4);
            dh[0] = z; dh[1] = z;
            if (lane == 0) g_x2w[gw] = __int_as_float(0x7f800000);  // +inf
        }
    } else if (gw < NDP + NQ) {
        int r = gw - NDP;
        float4 v = reinterpret_cast<const float4*>(q + (size_t)r * DIM)[lane];
        __half2* dh = reinterpret_cast<__half2*>(g_Ah + (size_t)r * DIM + lane * 4);
        dh[0] = __halves2half2(__float2half_rn(-2.f * v.x), __float2half_rn(-2.f * v.y));
        dh[1] = __halves2half2(__float2half_rn(-2.f * v.z), __float2half_rn(-2.f * v.w));
    }
}

// ---------------------------------------------------------------------------
// Kernel 2: 1-term HMMA GEMM -> g_s (fp16).  s[m,n] ~= (-2q_m).x_n + x2w[n]
// CTA = 128x128 tile, 256 threads / 8 warps, warp tile 64x32, 2 CTAs/SM.
// ---------------------------------------------------------------------------
#define SA_H 0
#define SB_H 32768
#define SX2  65536                     // 128 floats
#define SMEM_TOTAL (65536 + 512)

__global__ void __launch_bounds__(256, 2)
gemm_hmma_kernel() {
    extern __shared__ char smem[];
    const uint32_t sb = smem_u32(smem);
    const int t = threadIdx.x, lane = t & 31, wid = t >> 5;
    const int m0 = blockIdx.x * 128, n0 = blockIdx.y * 128;
    const int wm = (wid >> 2) * 64, wn = (wid & 3) * 32;

    if (t < 128) reinterpret_cast<float*>(smem + SX2)[t] = g_x2w[n0 + t];

    // stage Ah + Bh via cp.async (swizzled)
    #pragma unroll
    for (int i = 0; i < 16; i++) {
        int id = t + 256 * i;
        int tile = id >> 11;            // 0=Ah 1=Bh
        int within = id & 2047;
        int row = within >> 4, c = within & 15;
        const __half* src = tile ? g_Xh : g_Ah;
        int grow = (tile ? n0 : m0) + row;
        uint32_t dst = sb + (tile ? SB_H : SA_H) + row * 256 + swzc((uint32_t)c, row & 7) * 16;
        cp16(dst, reinterpret_cast<const char*>(src) + (size_t)grow * 256 + c * 16);
    }
    cp_commit();

    uint32_t aOff[4], aS[4];
    #pragma unroll
    for (int mf = 0; mf < 4; mf++) {
        int r = wm + mf * 16 + (lane & 15);
        aOff[mf] = (uint32_t)r * 256; aS[mf] = r & 7;
    }
    uint32_t bOff[2], bS[2];
    #pragma unroll
    for (int p = 0; p < 2; p++) {
        int r = wn + p * 16 + (lane & 7) + ((lane >> 4) << 3);
        bOff[p] = (uint32_t)r * 256; bS[p] = r & 7;
    }
    const uint32_t aHi = (lane >> 4) & 1;
    const uint32_t bHi = (lane >> 3) & 1;

    float acc[4][4][4];
    #pragma unroll
    for (int mf = 0; mf < 4; mf++)
        #pragma unroll
        for (int nf = 0; nf < 4; nf++)
            #pragma unroll
            for (int e = 0; e < 4; e++) acc[mf][nf][e] = 0.f;

    cp_wait0();
    __syncthreads();

    #pragma unroll
    for (int c8 = 0; c8 < 8; c8++) {
        uint32_t ah[4][4], bh[2][4];
        uint32_t ckA = 2 * c8 + aHi, ckB = 2 * c8 + bHi;
        #pragma unroll
        for (int mf = 0; mf < 4; mf++) ldsm4(ah[mf], sb + SA_H + aOff[mf] + swzc(ckA, aS[mf]) * 16);
        #pragma unroll
        for (int p = 0; p < 2; p++)    ldsm4(bh[p], sb + SB_H + bOff[p] + swzc(ckB, bS[p]) * 16);
        #pragma unroll
        for (int mf = 0; mf < 4; mf++)
            #pragma unroll
            for (int nf = 0; nf < 4; nf++)
                mma16816(acc[mf][nf], ah[mf], &bh[nf >> 1][(nf & 1) * 2]);
    }

    // epilogue: + x2w, convert to fp16, streaming 4B stores
    const int g = lane >> 2, tig = lane & 3;
    #pragma unroll
    for (int mf = 0; mf < 4; mf++) {
        int m = m0 + wm + mf * 16 + g;
        #pragma unroll
        for (int nf = 0; nf < 4; nf++) {
            int nl = wn + nf * 8 + tig * 2;
            float2 xw = *reinterpret_cast<const float2*>(smem + SX2 + nl * 4);
            __half2 h0 = __floats2half2_rn(acc[mf][nf][0] + xw.x, acc[mf][nf][1] + xw.y);
            __half2 h1 = __floats2half2_rn(acc[mf][nf][2] + xw.x, acc[mf][nf][3] + xw.y);
            stcs32(g_s + (size_t)m * NDP + n0 + nl,       *reinterpret_cast<uint32_t*>(&h0));
            stcs32(g_s + (size_t)(m + 8) * NDP + n0 + nl, *reinterpret_cast<uint32_t*>(&h1));
        }
    }
}

// ---------------------------------------------------------------------------
// Kernel 3: per-query approx top-32 over fp16 scores -> g_c32.
// uint4 = 16 bytes = 8 fp16 scores.  NDP/8 = 12512 exactly.
// ---------------------------------------------------------------------------
__global__ void __launch_bounds__(256, 1)
select_kernel() {
    const int b = blockIdx.x;
    const int t = threadIdx.x;
    const uint4* row8 = reinterpret_cast<const uint4*>(g_s + (size_t)b * NDP);

    float bv[KSEL];
    int   bi[KSEL];
    #pragma unroll
    for (int r = 0; r < KSEL; r++) { bv[r] = __int_as_float(0x7f800000); bi[r] = 0; }

    for (int j = t; j < NDP / 8; j += 256) {        // uint4 = 8 fp16 scores
        uint4 u = __ldcs(&row8[j]);
        uint32_t uu[4] = {u.x, u.y, u.z, u.w};
        int n = j * 8;
        #pragma unroll
        for (int p = 0; p < 4; p++) {
            __half2 h2 = *reinterpret_cast<__half2*>(&uu[p]);
            float2 f2 = __half22float2(h2);
            float vals[2] = {f2.x, f2.y};
            #pragma unroll
            for (int e = 0; e < 2; e++) {
                float x = vals[e];
                if (x < bv[KSEL - 1]) {
                    float cv = x; int ci = n + p * 2 + e;
                    #pragma unroll
                    for (int r = 0; r < KSEL; r++) {
                        if (cv < bv[r]) {
                            float tv = bv[r]; bv[r] = cv; cv = tv;
                            int ti = bi[r]; bi[r] = ci; ci = ti;
                        }
                    }
                }
            }
        }
    }

    __shared__ float sv[256 * (KSEL + 1)];
    __shared__ int   si[256 * (KSEL + 1)];
    __shared__ float redv[256];
    __shared__ int   redt[256];
    __shared__ float selv[M32];
    __shared__ int   seli[M32];

    #pragma unroll
    for (int r = 0; r < KSEL; r++) {
        sv[t * (KSEL + 1) + r] = bv[r];
        si[t * (KSEL + 1) + r] = bi[r];
    }
    sv[t * (KSEL + 1) + KSEL] = __int_as_float(0x7f800000);  // sentinel
    __syncthreads();

    int h = 0;
    for (int r = 0; r < M32; r++) {
        redv[t] = sv[t * (KSEL + 1) + h];
        redt[t] = t;
        __syncthreads();
        #pragma unroll
        for (int s = 128; s > 0; s >>= 1) {
            if (t < s) {
                if (redv[t + s] < redv[t]) { redv[t] = redv[t + s]; redt[t] = redt[t + s]; }
            }
            __syncthreads();
        }
        if (t == redt[0]) {
            selv[r] = sv[t * (KSEL + 1) + h];
            seli[r] = si[t * (KSEL + 1) + h];
            if (h < KSEL) h++;                    // clamp at sentinel
        }
        __syncthreads();
    }

    if (t < M32)
        g_c32[(size_t)b * M32 + t] = make_float2(selv[t], __int_as_float(seli[t]));
}

// ---------------------------------------------------------------------------
// Kernel 4: exact fp32 rescore of 32 candidates -> final outputs.
//   rank by d2 - w (same ordering as reference), top-10, argmax w - sqrt(d2).
// ---------------------------------------------------------------------------
__global__ void __launch_bounds__(128, 8)
rescore_kernel(const float* __restrict__ X, const float* __restrict__ q,
               const float* __restrict__ w, float* __restrict__ out) {
    const int b = blockIdx.x;
    const int t = threadIdx.x, lane = t & 31, wid = t >> 5;

    __shared__ float qs[DIM];
    __shared__ float cs[M32];    // srank = d2 - w
    __shared__ float cf[M32];    // f = w - sqrt(d2)
    __shared__ int   ci[M32];

    qs[t] = q[(size_t)b * DIM + t];
    __syncthreads();

    const float4* q4 = reinterpret_cast<const float4*>(qs);
    #pragma unroll
    for (int c = 0; c < 8; c++) {
        int slot = wid * 8 + c;
        int idx = __float_as_int(g_c32[(size_t)b * M32 + slot].y);
        float4 xv = reinterpret_cast<const float4*>(X + (size_t)idx * DIM)[lane];
        float4 qv = q4[lane];
        float dx = qv.x - xv.x, dy = qv.y - xv.y, dz = qv.z - xv.z, dw = qv.w - xv.w;
        float d = dx * dx + dy * dy + dz * dz + dw * dw;
        #pragma unroll
        for (int o = 16; o > 0; o >>= 1) d += __shfl_xor_sync(0xffffffffu, d, o);
        if (lane == 0) {
            float wn = w[idx];
            cs[slot] = d - wn;
            cf[slot] = wn - sqrtf(fmaxf(d, 0.0f));
            ci[slot] = idx;
        }
    }
    __syncthreads();

    if (t == 0) {
        float bv[KSEL]; int bs[KSEL];
        #pragma unroll
        for (int r = 0; r < KSEL; r++) { bv[r] = __int_as_float(0x7f800000); bs[r] = -1; }
        #pragma unroll
        for (int e = 0; e < M32; e++) {
            float x = cs[e];
            if (x < bv[KSEL - 1]) {
                float cv = x; int cslot = e;
                #pragma unroll
                for (int r = 0; r < KSEL; r++) {
                    if (cv < bv[r]) {
                        float tv = bv[r]; bv[r] = cv; cv = tv;
                        int ts = bs[r]; bs[r] = cslot; cslot = ts;
                    }
                }
            }
        }
        float bestf = __int_as_float(0xff800000);
        int besti = 0;
        #pragma unroll
        for (int r = 0; r < KSEL; r++) {
            int s = bs[r];
            if (s >= 0) {
                float f = cf[s];
                if (f > bestf) { bestf = f; besti = ci[s]; }
            }
        }
        out[b]      = bestf;
        out[NQ + b] = (float)besti;
    }
}

extern "C" void kernel_launch(void* const* d_in, const int* in_sizes, int n_in,
                              void* d_out, int out_size) {
    const float* q = (const float*)d_in[0];   // x_tilde [2048,128]
    const float* X = (const float*)d_in[1];   // X [100000,128]
    const float* w = (const float*)d_in[2];   // w [100000,1]
    float* out = (float*)d_out;

    cudaFuncSetAttribute(gemm_hmma_kernel,
                         cudaFuncAttributeMaxDynamicSharedMemorySize, SMEM_TOTAL);

    prep_kernel<<<(NDP + NQ) / 8, 256>>>(X, w, q);
    dim3 g(NQ / 128, NDP / 128);              // (16, 782): m fastest for L2 X reuse
    gemm_hmma_kernel<<<g, 256, SMEM_TOTAL>>>();
    select_kernel<<<NQ, 256>>>();
    rescore_kernel<<<NQ, 128>>>(X, q, w, out);
}